// round 1
// baseline (speedup 1.0000x reference)
#include <cuda_runtime.h>
#include <math_constants.h>

#define MPIX   32768      // 8*64*64 pixels
#define CIN    256
#define DQK    32
#define DV     128
#define NSEQ   4096
#define NB     8

// Scratch (allocation-free: __device__ globals)
__device__ float g_qkv[MPIX * 192];   // per pixel: [q(32) | k(32) | v(128)]
__device__ float g_o[MPIX * DV];      // attention output before Wo

// ---------------------------------------------------------------------------
// Kernel 1: projections  qkv = x @ [Wq|Wk|Wv] + [bq|bk|bv]
// GEMM M=32768, K=256, N=192. BM=64, BN=64, BK=16, 256 thr, 4x4 micro.
// ---------------------------------------------------------------------------
__global__ __launch_bounds__(256) void proj_kernel(
    const float* __restrict__ x,
    const float* __restrict__ Wq, const float* __restrict__ bq,
    const float* __restrict__ Wk, const float* __restrict__ bk,
    const float* __restrict__ Wv, const float* __restrict__ bv)
{
    __shared__ float As[16][68];   // transposed: As[k][m]
    __shared__ float Bs[16][68];   // Bs[k][n]

    const int t  = threadIdx.x;
    const int ty = t >> 4, tx = t & 15;
    const int m0 = blockIdx.x * 64;
    const int n0 = blockIdx.y * 64;

    const int arow = t >> 2, akq = (t & 3) * 4;
    const int bkk  = t >> 4, bnq = (t & 15) * 4;

    float acc[4][4] = {};

    for (int kt = 0; kt < CIN; kt += 16) {
        // A tile (transpose into smem)
        float4 av = *(const float4*)(x + (size_t)(m0 + arow) * CIN + kt + akq);
        As[akq + 0][arow] = av.x;
        As[akq + 1][arow] = av.y;
        As[akq + 2][arow] = av.z;
        As[akq + 3][arow] = av.w;
        // B tile: segmented weight select
        #pragma unroll
        for (int i = 0; i < 4; i++) {
            int gn = n0 + bnq + i;
            int gk = kt + bkk;
            float w;
            if (gn < 32)       w = Wq[gk * 32  + gn];
            else if (gn < 64)  w = Wk[gk * 32  + (gn - 32)];
            else               w = Wv[gk * 128 + (gn - 64)];
            Bs[bkk][bnq + i] = w;
        }
        __syncthreads();
        #pragma unroll
        for (int kk = 0; kk < 16; kk++) {
            float4 a = *(const float4*)&As[kk][ty * 4];
            float4 b = *(const float4*)&Bs[kk][tx * 4];
            float ar[4] = {a.x, a.y, a.z, a.w};
            float br[4] = {b.x, b.y, b.z, b.w};
            #pragma unroll
            for (int i = 0; i < 4; i++)
                #pragma unroll
                for (int j = 0; j < 4; j++)
                    acc[i][j] += ar[i] * br[j];
        }
        __syncthreads();
    }

    #pragma unroll
    for (int i = 0; i < 4; i++) {
        int gm = m0 + ty * 4 + i;
        #pragma unroll
        for (int j = 0; j < 4; j++) {
            int gn = n0 + tx * 4 + j;
            float bias;
            if (gn < 32)       bias = bq[gn];
            else if (gn < 64)  bias = bk[gn - 32];
            else               bias = bv[gn - 64];
            g_qkv[(size_t)gm * 192 + gn] = acc[i][j] + bias;
        }
    }
}

// ---------------------------------------------------------------------------
// Kernel 2: flash attention. MTILE=128 query rows, KTILE=128 keys per step.
// grid = 8 batches * 32 row tiles = 256 blocks, 256 threads.
// Dynamic smem layout:
//   Qs [32][132] (transposed, padded)
//   Ks [32][132]
//   Vs [128][128]
//   Ps [128][132]
//   corr_s[128], l_s[128]
// ---------------------------------------------------------------------------
#define QS_OFF   0
#define KS_OFF   (32 * 132)
#define VS_OFF   (KS_OFF + 32 * 132)
#define PS_OFF   (VS_OFF + 128 * 128)
#define CORR_OFF (PS_OFF + 128 * 132)
#define LS_OFF   (CORR_OFF + 128)
#define ATTN_SMEM_FLOATS (LS_OFF + 128)

__global__ __launch_bounds__(256, 1) void attn_kernel()
{
    extern __shared__ float sm[];
    float* Qs     = sm + QS_OFF;
    float* Ks     = sm + KS_OFF;
    float* Vs     = sm + VS_OFF;
    float* Ps     = sm + PS_OFF;
    float* corr_s = sm + CORR_OFF;
    float* l_s    = sm + LS_OFF;

    const int t  = threadIdx.x;
    const int ty = t >> 4, tx = t & 15;
    const int b  = blockIdx.x >> 5;
    const int mt = blockIdx.x & 31;
    const int m0 = mt * 128;
    const size_t base = (size_t)b * NSEQ;

    // Load Q tile transposed: Qs[kk][row]
    {
        const int lrow = t >> 3;
        const int lkq  = (t & 7) * 4;
        #pragma unroll
        for (int p = 0; p < 4; p++) {
            int r = p * 32 + lrow;
            float4 v = *(const float4*)(g_qkv + (base + m0 + r) * 192 + lkq);
            Qs[(lkq + 0) * 132 + r] = v.x;
            Qs[(lkq + 1) * 132 + r] = v.y;
            Qs[(lkq + 2) * 132 + r] = v.z;
            Qs[(lkq + 3) * 132 + r] = v.w;
        }
    }

    float o[8][8] = {};
    float m_i = -CUDART_INF_F;
    float l_i = 0.f;
    const int srow  = t >> 1;
    const int shalf = t & 1;

    for (int kt = 0; kt < 32; kt++) {
        const int j0 = kt * 128;
        // K tile (transposed)
        {
            const int lrow = t >> 3;
            const int lkq  = (t & 7) * 4;
            #pragma unroll
            for (int p = 0; p < 4; p++) {
                int r = p * 32 + lrow;
                float4 v = *(const float4*)(g_qkv + (base + j0 + r) * 192 + 32 + lkq);
                Ks[(lkq + 0) * 132 + r] = v.x;
                Ks[(lkq + 1) * 132 + r] = v.y;
                Ks[(lkq + 2) * 132 + r] = v.z;
                Ks[(lkq + 3) * 132 + r] = v.w;
            }
        }
        // V tile
        #pragma unroll
        for (int p = 0; p < 16; p++) {
            int fi = p * 256 + t;
            int r  = fi >> 5;
            int c  = (fi & 31) * 4;
            *(float4*)(Vs + r * 128 + c) =
                *(const float4*)(g_qkv + (base + j0 + r) * 192 + 64 + c);
        }
        __syncthreads();

        // Scores S = Q K^T  (8x8 micro-tiles)
        {
            float s[8][8] = {};
            #pragma unroll
            for (int kk = 0; kk < 32; kk++) {
                float4 qa = *(const float4*)(Qs + kk * 132 + ty * 8);
                float4 qb = *(const float4*)(Qs + kk * 132 + ty * 8 + 4);
                float4 ka = *(const float4*)(Ks + kk * 132 + tx * 8);
                float4 kb = *(const float4*)(Ks + kk * 132 + tx * 8 + 4);
                float qr[8] = {qa.x, qa.y, qa.z, qa.w, qb.x, qb.y, qb.z, qb.w};
                float kr[8] = {ka.x, ka.y, ka.z, ka.w, kb.x, kb.y, kb.z, kb.w};
                #pragma unroll
                for (int i = 0; i < 8; i++)
                    #pragma unroll
                    for (int j = 0; j < 8; j++)
                        s[i][j] += qr[i] * kr[j];
            }
            #pragma unroll
            for (int i = 0; i < 8; i++) {
                *(float4*)(Ps + (ty * 8 + i) * 132 + tx * 8) =
                    make_float4(s[i][0], s[i][1], s[i][2], s[i][3]);
                *(float4*)(Ps + (ty * 8 + i) * 132 + tx * 8 + 4) =
                    make_float4(s[i][4], s[i][5], s[i][6], s[i][7]);
            }
        }
        __syncthreads();

        // Online softmax (2 threads per row, 64 cols each)
        {
            float* prow = Ps + srow * 132 + shalf * 64;
            float mx = -CUDART_INF_F;
            #pragma unroll 8
            for (int c = 0; c < 64; c++) mx = fmaxf(mx, prow[c]);
            mx = fmaxf(mx, __shfl_xor_sync(0xffffffffu, mx, 1));
            float m_new = fmaxf(m_i, mx);
            float corr  = __expf(m_i - m_new);
            float sum = 0.f;
            #pragma unroll 8
            for (int c = 0; c < 64; c++) {
                float p = __expf(prow[c] - m_new);
                prow[c] = p;
                sum += p;
            }
            sum += __shfl_xor_sync(0xffffffffu, sum, 1);
            l_i = l_i * corr + sum;
            m_i = m_new;
            if (shalf == 0) corr_s[srow] = corr;
        }
        __syncthreads();

        // O = O*corr + P @ V
        {
            float cr[8];
            #pragma unroll
            for (int i = 0; i < 8; i++) cr[i] = corr_s[ty * 8 + i];
            #pragma unroll
            for (int i = 0; i < 8; i++)
                #pragma unroll
                for (int j = 0; j < 8; j++)
                    o[i][j] *= cr[i];

            #pragma unroll 2
            for (int jj = 0; jj < 128; jj++) {
                float p[8], v[8];
                #pragma unroll
                for (int i = 0; i < 8; i++) p[i] = Ps[(ty * 8 + i) * 132 + jj];
                #pragma unroll
                for (int j = 0; j < 8; j++) v[j] = Vs[jj * 128 + tx + j * 16];
                #pragma unroll
                for (int i = 0; i < 8; i++)
                    #pragma unroll
                    for (int j = 0; j < 8; j++)
                        o[i][j] += p[i] * v[j];
            }
        }
        __syncthreads();
    }

    if (shalf == 0) l_s[srow] = l_i;
    __syncthreads();

    #pragma unroll
    for (int i = 0; i < 8; i++) {
        float linv = 1.f / l_s[ty * 8 + i];
        #pragma unroll
        for (int j = 0; j < 8; j++) {
            g_o[(base + m0 + ty * 8 + i) * DV + tx + j * 16] = o[i][j] * linv;
        }
    }
}

// ---------------------------------------------------------------------------
// Kernel 3: epilogue  out = g_o @ Wo + bo + x
// GEMM M=32768, K=128, N=256. Same tiling as proj.
// ---------------------------------------------------------------------------
__global__ __launch_bounds__(256) void epi_kernel(
    const float* __restrict__ x,
    const float* __restrict__ Wo, const float* __restrict__ bo,
    float* __restrict__ out)
{
    __shared__ float As[16][68];
    __shared__ float Bs[16][68];

    const int t  = threadIdx.x;
    const int ty = t >> 4, tx = t & 15;
    const int m0 = blockIdx.x * 64;
    const int n0 = blockIdx.y * 64;

    const int arow = t >> 2, akq = (t & 3) * 4;
    const int bkk  = t >> 4, bnq = (t & 15) * 4;

    float acc[4][4] = {};

    for (int kt = 0; kt < DV; kt += 16) {
        float4 av = *(const float4*)(g_o + (size_t)(m0 + arow) * DV + kt + akq);
        As[akq + 0][arow] = av.x;
        As[akq + 1][arow] = av.y;
        As[akq + 2][arow] = av.z;
        As[akq + 3][arow] = av.w;
        float4 bv = *(const float4*)(Wo + (size_t)(kt + bkk) * 256 + n0 + bnq);
        *(float4*)&Bs[bkk][bnq] = bv;
        __syncthreads();
        #pragma unroll
        for (int kk = 0; kk < 16; kk++) {
            float4 a = *(const float4*)&As[kk][ty * 4];
            float4 b = *(const float4*)&Bs[kk][tx * 4];
            float ar[4] = {a.x, a.y, a.z, a.w};
            float br[4] = {b.x, b.y, b.z, b.w};
            #pragma unroll
            for (int i = 0; i < 4; i++)
                #pragma unroll
                for (int j = 0; j < 4; j++)
                    acc[i][j] += ar[i] * br[j];
        }
        __syncthreads();
    }

    const int gn = n0 + tx * 4;
    float4 bias = *(const float4*)(bo + gn);
    #pragma unroll
    for (int i = 0; i < 4; i++) {
        int gm = m0 + ty * 4 + i;
        float4 xr = *(const float4*)(x + (size_t)gm * 256 + gn);
        float4 r;
        r.x = acc[i][0] + bias.x + xr.x;
        r.y = acc[i][1] + bias.y + xr.y;
        r.z = acc[i][2] + bias.z + xr.z;
        r.w = acc[i][3] + bias.w + xr.w;
        *(float4*)(out + (size_t)gm * 256 + gn) = r;
    }
}

// ---------------------------------------------------------------------------
extern "C" void kernel_launch(void* const* d_in, const int* in_sizes, int n_in,
                              void* d_out, int out_size)
{
    const float* x  = (const float*)d_in[0];
    const float* Wq = (const float*)d_in[1];
    const float* bq = (const float*)d_in[2];
    const float* Wk = (const float*)d_in[3];
    const float* bk = (const float*)d_in[4];
    const float* Wv = (const float*)d_in[5];
    const float* bv = (const float*)d_in[6];
    const float* Wo = (const float*)d_in[7];
    const float* bo = (const float*)d_in[8];
    float* out = (float*)d_out;

    const int attn_smem = ATTN_SMEM_FLOATS * (int)sizeof(float);  // ~164 KB
    cudaFuncSetAttribute(attn_kernel,
                         cudaFuncAttributeMaxDynamicSharedMemorySize, attn_smem);

    proj_kernel<<<dim3(512, 3), 256>>>(x, Wq, bq, Wk, bk, Wv, bv);
    attn_kernel<<<256, 256, attn_smem>>>();
    epi_kernel<<<dim3(512, 4), 256>>>(x, Wo, bo, out);
}